// round 5
// baseline (speedup 1.0000x reference)
#include <cuda_runtime.h>

// Problem constants (fixed shapes)
#define BB 4
#define NN 2048
#define DD 1024
#define HH 16
#define HD 64
#define NCTXMAX 512
#define MTOT (BB*NN)          // 8192 rows

// -------- scratch (static device globals; no allocation allowed) ----------
__device__ float g_q[BB*HH*NN*HD];    // [B,H,N,hd]
__device__ float g_k[BB*HH*NN*HD];
__device__ float g_v[BB*HH*NN*HD];    // gated V
__device__ float g_ao[(size_t)MTOT*DD]; // attention output, [B,N,D]
__device__ float g_gate[MTOT];
__device__ float g_bias[MTOT];

// ---------------------------------------------------------------------------
// Kernel 0: per-token gate + logit column bias
// ---------------------------------------------------------------------------
__global__ void gate_bias_kernel(const float* __restrict__ ppr,
                                 const float* __restrict__ trust,
                                 const float* __restrict__ alpha,
                                 const float* __restrict__ tsc,
                                 const int* __restrict__ nctx_p) {
    int i = blockIdx.x * blockDim.x + threadIdx.x;
    if (i >= MTOT) return;
    int b = i >> 11;          // /NN
    int n = i & (NN - 1);

    int nctx = NCTXMAX;
    if (nctx_p) {
        int raw = *nctx_p;
        if (raw >= 0 && raw <= 4096) {
            nctx = raw;
        } else {
            float f = __int_as_float(raw);
            if (f >= 0.f && f <= 4096.f) nctx = (int)f;
        }
    }
    if (nctx > NCTXMAX) nctx = NCTXMAX;

    float gate = 1.f, bias = 0.f;
    if (n < nctx) {
        float t = tsc[0] * trust[b * NCTXMAX + n];
        gate = 1.f / (1.f + __expf(-t));
        float p = fmaxf(ppr[b * NCTXMAX + n], 1e-8f);
        bias = -alpha[0] * __logf(p);
    }
    g_gate[i] = gate;
    g_bias[i] = bias;
}

// ---------------------------------------------------------------------------
// Generic 128x128x8 fp32 SGEMM, 256 threads, 8x8 per thread.
// MODE 0: C = x @ W_in + b_in, scattered into g_q/g_k/g_v ([B,H,N,hd]),
//         with the trust gate applied to V rows.
// MODE 1: C = g_ao @ W_out + b_out, written densely to Cout ([M, NC]).
// ---------------------------------------------------------------------------
template<int NC, int MODE>
__global__ __launch_bounds__(256)
void gemm_kernel(const float* __restrict__ A,
                 const float* __restrict__ W,
                 const float* __restrict__ bias,
                 float* __restrict__ Cout) {
    const int K = DD;
    __shared__ float As[8][128];
    __shared__ float Bs[8][128];

    const int bm = blockIdx.y * 128;
    const int bn = blockIdx.x * 128;
    const int tid = threadIdx.x;

    const int ar  = tid >> 1;           // 0..127  (A tile row)
    const int ak  = (tid & 1) << 2;     // 0 or 4  (A tile k)
    const int bkr = tid >> 5;           // 0..7    (B tile k)
    const int bc  = (tid & 31) << 2;    // 0..124  (B tile col)
    const int tx  = tid & 15;
    const int ty  = tid >> 4;

    const float* Ap = (MODE == 1) ? (const float*)g_ao : A;

    float acc[8][8];
#pragma unroll
    for (int i = 0; i < 8; i++)
#pragma unroll
        for (int j = 0; j < 8; j++) acc[i][j] = 0.f;

    const float* Aptr = Ap + (size_t)(bm + ar) * K + ak;
    const float* Wptr = W + (size_t)bkr * NC + bn + bc;

    for (int k0 = 0; k0 < K; k0 += 8) {
        float4 av = *(const float4*)(Aptr + k0);
        float4 wv = *(const float4*)(Wptr + (size_t)k0 * NC);
        As[ak + 0][ar] = av.x;
        As[ak + 1][ar] = av.y;
        As[ak + 2][ar] = av.z;
        As[ak + 3][ar] = av.w;
        *(float4*)&Bs[bkr][bc] = wv;
        __syncthreads();

#pragma unroll
        for (int kk = 0; kk < 8; kk++) {
            float a[8], bb[8];
            *(float4*)(a)     = *(const float4*)&As[kk][ty * 8];
            *(float4*)(a + 4) = *(const float4*)&As[kk][ty * 8 + 4];
            *(float4*)(bb)     = *(const float4*)&Bs[kk][tx * 8];
            *(float4*)(bb + 4) = *(const float4*)&Bs[kk][tx * 8 + 4];
#pragma unroll
            for (int i = 0; i < 8; i++)
#pragma unroll
                for (int j = 0; j < 8; j++)
                    acc[i][j] = fmaf(a[i], bb[j], acc[i][j]);
        }
        __syncthreads();
    }

    if (MODE == 0) {
        // scatter to q/k/v with [B,H,N,hd] layout; gate V
#pragma unroll
        for (int i = 0; i < 8; i++) {
            int r = bm + ty * 8 + i;
            int b = r >> 11;
            int n = r & (NN - 1);
            float gt = g_gate[r];
#pragma unroll
            for (int j = 0; j < 8; j++) {
                int c = bn + tx * 8 + j;
                float val = acc[i][j] + bias[c];
                int which = c >> 10;       // 0=q 1=k 2=v
                int dd = c & 1023;
                int h = dd >> 6;
                int hd = dd & 63;
                int idx = ((b * HH + h) * NN + n) * HD + hd;
                if (which == 0)      g_q[idx] = val;
                else if (which == 1) g_k[idx] = val;
                else                 g_v[idx] = val * gt;
            }
        }
    } else {
#pragma unroll
        for (int i = 0; i < 8; i++) {
            int r = bm + ty * 8 + i;
            size_t base = (size_t)r * NC + bn + tx * 8;
            float4 o0, o1;
            o0.x = acc[i][0] + bias[bn + tx * 8 + 0];
            o0.y = acc[i][1] + bias[bn + tx * 8 + 1];
            o0.z = acc[i][2] + bias[bn + tx * 8 + 2];
            o0.w = acc[i][3] + bias[bn + tx * 8 + 3];
            o1.x = acc[i][4] + bias[bn + tx * 8 + 4];
            o1.y = acc[i][5] + bias[bn + tx * 8 + 5];
            o1.z = acc[i][6] + bias[bn + tx * 8 + 6];
            o1.w = acc[i][7] + bias[bn + tx * 8 + 7];
            *(float4*)&Cout[base]     = o0;
            *(float4*)&Cout[base + 4] = o1;
        }
    }
}

// ---------------------------------------------------------------------------
// Flash attention, fp32. Grid (N/64, H, B), 128 threads.
// Q tile 64 rows, key tiles of 32, online softmax, column bias on logits.
// Q and K stored transposed in smem for conflict-free float4 reads.
// ---------------------------------------------------------------------------
__global__ __launch_bounds__(128)
void attn_kernel() {
    __shared__ float Qt[64][68];    // [k][query row]
    __shared__ float Kt[64][36];    // [k][key]
    __shared__ float Vs[32][68];    // [key][hd]
    __shared__ float Pst[32][68];   // [key][query row]
    __shared__ float rowm[64], rowl[64], rowscale[64];
    __shared__ float biass[32];

    const int b = blockIdx.z;
    const int h = blockIdx.y;
    const int q0 = blockIdx.x * 64;
    const int tid = threadIdx.x;

    const float* Qg = g_q + (size_t)(b * HH + h) * NN * HD;
    const float* Kg = g_k + (size_t)(b * HH + h) * NN * HD;
    const float* Vg = g_v + (size_t)(b * HH + h) * NN * HD;
    const float* biasg = g_bias + b * NN;

    // load Q tile transposed: Qt[hd][row]
    for (int t = tid; t < 64 * 16; t += 128) {
        int r = t >> 4;
        int c4 = (t & 15) << 2;
        float4 v = *(const float4*)&Qg[(q0 + r) * HD + c4];
        Qt[c4 + 0][r] = v.x;
        Qt[c4 + 1][r] = v.y;
        Qt[c4 + 2][r] = v.z;
        Qt[c4 + 3][r] = v.w;
    }
    if (tid < 64) { rowm[tid] = -1e30f; rowl[tid] = 0.f; }

    const int tx = tid & 7;        // S: key group / O: col group
    const int ty = tid >> 3;       // row group (0..15)
    const int r0 = ty * 4;         // 4 query rows
    const int c0 = tx * 4;         // 4 keys (S phase)
    const int oc0 = tx * 8;        // 8 output cols (O phase)

    float o[4][8];
#pragma unroll
    for (int i = 0; i < 4; i++)
#pragma unroll
        for (int j = 0; j < 8; j++) o[i][j] = 0.f;

    const float scale = 0.125f;    // 1/sqrt(64)
    __syncthreads();

    for (int kt = 0; kt < NN; kt += 32) {
        // load K transposed + V row-major + bias slice
        for (int t = tid; t < 32 * 16; t += 128) {
            int r = t >> 4;              // key 0..31
            int c4 = (t & 15) << 2;      // hd
            float4 kv = *(const float4*)&Kg[(kt + r) * HD + c4];
            Kt[c4 + 0][r] = kv.x;
            Kt[c4 + 1][r] = kv.y;
            Kt[c4 + 2][r] = kv.z;
            Kt[c4 + 3][r] = kv.w;
            float4 vv = *(const float4*)&Vg[(kt + r) * HD + c4];
            *(float4*)&Vs[r][c4] = vv;
        }
        if (tid < 32) biass[tid] = biasg[kt + tid];
        __syncthreads();

        // ---- S = Q K^T (4 rows x 4 keys per thread) ----
        float s[4][4];
#pragma unroll
        for (int i = 0; i < 4; i++)
#pragma unroll
            for (int j = 0; j < 4; j++) s[i][j] = 0.f;

#pragma unroll 8
        for (int k = 0; k < 64; k++) {
            float4 qa = *(const float4*)&Qt[k][r0];
            float4 kb = *(const float4*)&Kt[k][c0];
            s[0][0] = fmaf(qa.x, kb.x, s[0][0]);
            s[0][1] = fmaf(qa.x, kb.y, s[0][1]);
            s[0][2] = fmaf(qa.x, kb.z, s[0][2]);
            s[0][3] = fmaf(qa.x, kb.w, s[0][3]);
            s[1][0] = fmaf(qa.y, kb.x, s[1][0]);
            s[1][1] = fmaf(qa.y, kb.y, s[1][1]);
            s[1][2] = fmaf(qa.y, kb.z, s[1][2]);
            s[1][3] = fmaf(qa.y, kb.w, s[1][3]);
            s[2][0] = fmaf(qa.z, kb.x, s[2][0]);
            s[2][1] = fmaf(qa.z, kb.y, s[2][1]);
            s[2][2] = fmaf(qa.z, kb.z, s[2][2]);
            s[2][3] = fmaf(qa.z, kb.w, s[2][3]);
            s[3][0] = fmaf(qa.w, kb.x, s[3][0]);
            s[3][1] = fmaf(qa.w, kb.y, s[3][1]);
            s[3][2] = fmaf(qa.w, kb.z, s[3][2]);
            s[3][3] = fmaf(qa.w, kb.w, s[3][3]);
        }

        // ---- online softmax row stats + P (transposed) ----
        float bv0 = biass[c0 + 0];
        float bv1 = biass[c0 + 1];
        float bv2 = biass[c0 + 2];
        float bv3 = biass[c0 + 3];
#pragma unroll
        for (int i = 0; i < 4; i++) {
            float sv0 = fmaf(s[i][0], scale, bv0);
            float sv1 = fmaf(s[i][1], scale, bv1);
            float sv2 = fmaf(s[i][2], scale, bv2);
            float sv3 = fmaf(s[i][3], scale, bv3);
            float tm = fmaxf(fmaxf(sv0, sv1), fmaxf(sv2, sv3));
            tm = fmaxf(tm, __shfl_xor_sync(0xffffffffu, tm, 1));
            tm = fmaxf(tm, __shfl_xor_sync(0xffffffffu, tm, 2));
            tm = fmaxf(tm, __shfl_xor_sync(0xffffffffu, tm, 4));
            float mo = rowm[r0 + i];
            float mn = fmaxf(mo, tm);
            float p0 = __expf(sv0 - mn);
            float p1 = __expf(sv1 - mn);
            float p2 = __expf(sv2 - mn);
            float p3 = __expf(sv3 - mn);
            float rs = (p0 + p1) + (p2 + p3);
            rs += __shfl_xor_sync(0xffffffffu, rs, 1);
            rs += __shfl_xor_sync(0xffffffffu, rs, 2);
            rs += __shfl_xor_sync(0xffffffffu, rs, 4);
            if (tx == 0) {
                float sc = __expf(mo - mn);
                rowscale[r0 + i] = sc;
                rowm[r0 + i] = mn;
                rowl[r0 + i] = rowl[r0 + i] * sc + rs;
            }
            // store transposed: Pst[key][row]; components must be rows -> need
            // per-key stores of the 4 row values. Collect row i into temp; do
            // the transposed store after accumulating all 4 rows below.
            // Instead: write scalars here (4 per row) — transposed.
            Pst[c0 + 0][r0 + i] = p0;
            Pst[c0 + 1][r0 + i] = p1;
            Pst[c0 + 2][r0 + i] = p2;
            Pst[c0 + 3][r0 + i] = p3;
        }
        __syncthreads();

        // ---- O = O*scale + P V  (4 rows x 8 cols per thread) ----
        float sc0 = rowscale[r0 + 0];
        float sc1 = rowscale[r0 + 1];
        float sc2 = rowscale[r0 + 2];
        float sc3 = rowscale[r0 + 3];
#pragma unroll
        for (int j = 0; j < 8; j++) {
            o[0][j] *= sc0;
            o[1][j] *= sc1;
            o[2][j] *= sc2;
            o[3][j] *= sc3;
        }
#pragma unroll 8
        for (int k = 0; k < 32; k++) {
            float4 pa = *(const float4*)&Pst[k][r0];
            float4 v0 = *(const float4*)&Vs[k][oc0];
            float4 v1 = *(const float4*)&Vs[k][oc0 + 4];
            o[0][0] = fmaf(pa.x, v0.x, o[0][0]);
            o[0][1] = fmaf(pa.x, v0.y, o[0][1]);
            o[0][2] = fmaf(pa.x, v0.z, o[0][2]);
            o[0][3] = fmaf(pa.x, v0.w, o[0][3]);
            o[0][4] = fmaf(pa.x, v1.x, o[0][4]);
            o[0][5] = fmaf(pa.x, v1.y, o[0][5]);
            o[0][6] = fmaf(pa.x, v1.z, o[0][6]);
            o[0][7] = fmaf(pa.x, v1.w, o[0][7]);
            o[1][0] = fmaf(pa.y, v0.x, o[1][0]);
            o[1][1] = fmaf(pa.y, v0.y, o[1][1]);
            o[1][2] = fmaf(pa.y, v0.z, o[1][2]);
            o[1][3] = fmaf(pa.y, v0.w, o[1][3]);
            o[1][4] = fmaf(pa.y, v1.x, o[1][4]);
            o[1][5] = fmaf(pa.y, v1.y, o[1][5]);
            o[1][6] = fmaf(pa.y, v1.z, o[1][6]);
            o[1][7] = fmaf(pa.y, v1.w, o[1][7]);
            o[2][0] = fmaf(pa.z, v0.x, o[2][0]);
            o[2][1] = fmaf(pa.z, v0.y, o[2][1]);
            o[2][2] = fmaf(pa.z, v0.z, o[2][2]);
            o[2][3] = fmaf(pa.z, v0.w, o[2][3]);
            o[2][4] = fmaf(pa.z, v1.x, o[2][4]);
            o[2][5] = fmaf(pa.z, v1.y, o[2][5]);
            o[2][6] = fmaf(pa.z, v1.z, o[2][6]);
            o[2][7] = fmaf(pa.z, v1.w, o[2][7]);
            o[3][0] = fmaf(pa.w, v0.x, o[3][0]);
            o[3][1] = fmaf(pa.w, v0.y, o[3][1]);
            o[3][2] = fmaf(pa.w, v0.z, o[3][2]);
            o[3][3] = fmaf(pa.w, v0.w, o[3][3]);
            o[3][4] = fmaf(pa.w, v1.x, o[3][4]);
            o[3][5] = fmaf(pa.w, v1.y, o[3][5]);
            o[3][6] = fmaf(pa.w, v1.z, o[3][6]);
            o[3][7] = fmaf(pa.w, v1.w, o[3][7]);
        }
        __syncthreads();
    }

    // finalize: divide by l, write to g_ao [B,N,D]
#pragma unroll
    for (int i = 0; i < 4; i++) {
        float inv = 1.f / rowl[r0 + i];
        size_t base = ((size_t)(b * NN + q0 + r0 + i)) * DD + h * HD + oc0;
        float4 w0, w1;
        w0.x = o[i][0] * inv; w0.y = o[i][1] * inv;
        w0.z = o[i][2] * inv; w0.w = o[i][3] * inv;
        w1.x = o[i][4] * inv; w1.y = o[i][5] * inv;
        w1.z = o[i][6] * inv; w1.w = o[i][7] * inv;
        *(float4*)&g_ao[base]     = w0;
        *(float4*)&g_ao[base + 4] = w1;
    }
}

// ---------------------------------------------------------------------------
extern "C" void kernel_launch(void* const* d_in, const int* in_sizes, int n_in,
                              void* d_out, int out_size) {
    const float* x      = (const float*)d_in[0];
    const float* ppr    = (const float*)d_in[1];
    const float* trust  = (const float*)d_in[2];
    const float* W_in   = (const float*)d_in[3];
    const float* b_in   = (const float*)d_in[4];
    const float* W_out  = (const float*)d_in[5];
    const float* b_out  = (const float*)d_in[6];
    const float* alpha  = (const float*)d_in[7];
    const float* tsc    = (const float*)d_in[8];
    const int*   nctx_p = (n_in > 9) ? (const int*)d_in[9] : nullptr;
    float* out = (float*)d_out;

    gate_bias_kernel<<<(MTOT + 255) / 256, 256>>>(ppr, trust, alpha, tsc, nctx_p);
    gemm_kernel<3 * DD, 0><<<dim3(24, 64), 256>>>(x, W_in, b_in, nullptr);
    attn_kernel<<<dim3(NN / 64, HH, BB), 128>>>();
    gemm_kernel<DD, 1><<<dim3(8, 64), 256>>>(nullptr, W_out, b_out, out);
}

// round 7
// speedup vs baseline: 3.2850x; 3.2850x over previous
#include <cuda_runtime.h>
#include <cuda_bf16.h>
#include <cstdint>

// Problem constants (fixed shapes)
#define BB 4
#define NN 2048
#define DD 1024
#define HH 16
#define HD 64
#define NCTXMAX 512
#define MTOT (BB*NN)          // 8192 rows

// ---------------- scratch (static device globals) --------------------------
__device__ float g_gate[MTOT];
__device__ float g_bias[MTOT];
// bf16 hi/lo splits
__device__ __nv_bfloat16 gx0[(size_t)MTOT * DD],  gx1[(size_t)MTOT * DD];    // x
__device__ __nv_bfloat16 gq0[(size_t)MTOT * DD],  gq1[(size_t)MTOT * DD];    // [B,H,N,64]
__device__ __nv_bfloat16 gk0[(size_t)MTOT * DD],  gk1[(size_t)MTOT * DD];
__device__ __nv_bfloat16 gv0[(size_t)MTOT * DD],  gv1[(size_t)MTOT * DD];    // gated
__device__ __nv_bfloat16 gao0[(size_t)MTOT * DD], gao1[(size_t)MTOT * DD];   // [B*N, D]
__device__ __nv_bfloat16 gwin_t0[3 * DD * DD],  gwin_t1[3 * DD * DD];        // [3D x D]
__device__ __nv_bfloat16 gwout_t0[DD * DD],     gwout_t1[DD * DD];           // [D x D]

// ---------------- PTX helpers (base sm_103-safe only) ----------------------
__device__ __forceinline__ uint32_t smem_to_u32(const void* p) {
    uint32_t a;
    asm("{ .reg .u64 t; cvta.to.shared.u64 t, %1; cvt.u32.u64 %0, t; }"
        : "=r"(a) : "l"(p));
    return a;
}

#define CP_ASYNC16(saddr, gptr) \
    asm volatile("cp.async.cg.shared.global [%0], [%1], 16;" \
                 :: "r"((uint32_t)(saddr)), "l"((const void*)(gptr)) : "memory")
#define CP_COMMIT()  asm volatile("cp.async.commit_group;" ::: "memory")
#define CP_WAIT0()   asm volatile("cp.async.wait_group 0;" ::: "memory")
#define CP_WAIT1()   asm volatile("cp.async.wait_group 1;" ::: "memory")

__device__ __forceinline__ void ldmx4(uint32_t* r, uint32_t addr) {
    asm volatile("ldmatrix.sync.aligned.m8n8.x4.shared.b16 {%0,%1,%2,%3}, [%4];"
        : "=r"(r[0]), "=r"(r[1]), "=r"(r[2]), "=r"(r[3]) : "r"(addr));
}
__device__ __forceinline__ void ldmx2(uint32_t* r, uint32_t addr) {
    asm volatile("ldmatrix.sync.aligned.m8n8.x2.shared.b16 {%0,%1}, [%2];"
        : "=r"(r[0]), "=r"(r[1]) : "r"(addr));
}
__device__ __forceinline__ void ldmx2t(uint32_t* r, uint32_t addr) {
    asm volatile("ldmatrix.sync.aligned.m8n8.x2.trans.shared.b16 {%0,%1}, [%2];"
        : "=r"(r[0]), "=r"(r[1]) : "r"(addr));
}
__device__ __forceinline__ void mma16816(float* d, const uint32_t* a, const uint32_t* b) {
    asm volatile("mma.sync.aligned.m16n8k16.row.col.f32.bf16.bf16.f32 "
        "{%0,%1,%2,%3}, {%4,%5,%6,%7}, {%8,%9}, {%0,%1,%2,%3};"
        : "+f"(d[0]), "+f"(d[1]), "+f"(d[2]), "+f"(d[3])
        : "r"(a[0]), "r"(a[1]), "r"(a[2]), "r"(a[3]), "r"(b[0]), "r"(b[1]));
}

// split two fp32 into packed bf16x2 hi + bf16x2 lo (element0 in low half)
__device__ __forceinline__ void split2(float x, float y, uint32_t& hi, uint32_t& lo) {
    __nv_bfloat162 h = __floats2bfloat162_rn(x, y);
    float rx = x - __bfloat162float(h.x);
    float ry = y - __bfloat162float(h.y);
    __nv_bfloat162 l = __floats2bfloat162_rn(rx, ry);
    hi = *(uint32_t*)&h;
    lo = *(uint32_t*)&l;
}

// ---------------------------------------------------------------------------
// Kernel 0: per-token gate + logit column bias
// ---------------------------------------------------------------------------
__global__ void gate_bias_kernel(const float* __restrict__ ppr,
                                 const float* __restrict__ trust,
                                 const float* __restrict__ alpha,
                                 const float* __restrict__ tsc,
                                 const int* __restrict__ nctx_p) {
    int i = blockIdx.x * blockDim.x + threadIdx.x;
    if (i >= MTOT) return;
    int b = i >> 11;
    int n = i & (NN - 1);

    int nctx = NCTXMAX;
    if (nctx_p) {
        int raw = *nctx_p;
        if (raw >= 0 && raw <= 4096) {
            nctx = raw;
        } else {
            float f = __int_as_float(raw);
            if (f >= 0.f && f <= 4096.f) nctx = (int)f;
        }
    }
    if (nctx > NCTXMAX) nctx = NCTXMAX;

    float gate = 1.f, bias = 0.f;
    if (n < nctx) {
        float t = tsc[0] * trust[b * NCTXMAX + n];
        gate = 1.f / (1.f + __expf(-t));
        float p = fmaxf(ppr[b * NCTXMAX + n], 1e-8f);
        bias = -alpha[0] * __logf(p);
    }
    g_gate[i] = gate;
    g_bias[i] = bias;
}

// ---------------------------------------------------------------------------
// x (fp32 row-major) -> gx0/gx1 bf16 hi/lo
// ---------------------------------------------------------------------------
__global__ void split_x_kernel(const float* __restrict__ in) {
    size_t i = (size_t)blockIdx.x * blockDim.x + threadIdx.x;   // one float4
    float4 v = *(const float4*)(in + i * 4);
    uint32_t h0, l0, h1, l1;
    split2(v.x, v.y, h0, l0);
    split2(v.z, v.w, h1, l1);
    *(uint2*)(gx0 + i * 4) = make_uint2(h0, h1);
    *(uint2*)(gx1 + i * 4) = make_uint2(l0, l1);
}

// ---------------------------------------------------------------------------
// Transpose + split: W [K=1024 x NCv] fp32 -> Wt0/Wt1 [NCv x 1024] bf16
// ---------------------------------------------------------------------------
__global__ void tsplit_kernel(const float* __restrict__ in, int NCv, int which) {
    __shared__ float t[32][33];
    int n0 = blockIdx.x * 32, k0 = blockIdx.y * 32;
    int tx = threadIdx.x, ty = threadIdx.y;   // (32, 8)
#pragma unroll
    for (int i = 0; i < 4; i++) {
        int r = ty + i * 8;
        t[r][tx] = in[(size_t)(k0 + r) * NCv + n0 + tx];
    }
    __syncthreads();
    __nv_bfloat16* o0 = which ? gwout_t0 : gwin_t0;
    __nv_bfloat16* o1 = which ? gwout_t1 : gwin_t1;
#pragma unroll
    for (int i = 0; i < 4; i++) {
        int row = ty + i * 8;
        float v = t[tx][row];
        __nv_bfloat16 h0 = __float2bfloat16(v);
        __nv_bfloat16 h1 = __float2bfloat16(v - __bfloat162float(h0));
        size_t o = (size_t)(n0 + row) * 1024 + k0 + tx;
        o0[o] = h0;
        o1[o] = h1;
    }
}

// ---------------------------------------------------------------------------
// Stage loader for GEMM: A0/A1 rows [bm..bm+127], B0/B1 rows [bn..bn+127],
// k-chunk of 64 bf16 per row, xor-swizzled (chunk ^ (row&7)), via cp.async.
// Stage layout: A0 @ 0, A1 @ 16K, B0 @ 32K, B1 @ 48K (each 16KB).
// ---------------------------------------------------------------------------
__device__ __forceinline__ void gemm_load_stage(
    uint32_t sbase, int tid, int bm, int bn, int k0,
    const __nv_bfloat16* __restrict__ A0, const __nv_bfloat16* __restrict__ A1,
    const __nv_bfloat16* __restrict__ B0, const __nv_bfloat16* __restrict__ B1) {
#pragma unroll
    for (int p = 0; p < 4; p++) {
        int idx = tid + p * 256;
        int r = idx >> 3, c = idx & 7;
        uint32_t soff = (uint32_t)(r * 128 + ((c ^ (r & 7)) << 4));
        size_t ao = ((size_t)(bm + r) << 10) + k0 + c * 8;
        size_t bo = ((size_t)(bn + r) << 10) + k0 + c * 8;
        CP_ASYNC16(sbase + soff,         A0 + ao);
        CP_ASYNC16(sbase + 16384 + soff, A1 + ao);
        CP_ASYNC16(sbase + 32768 + soff, B0 + bo);
        CP_ASYNC16(sbase + 49152 + soff, B1 + bo);
    }
}

// ---------------------------------------------------------------------------
// mma.sync bf16x3 GEMM: C[128x128] = A(fp32 as hi+lo bf16) @ Wt^T (+bias)
// 256 threads (8 warps, 2m x 4n), warp tile 64x32, K=1024 in 16 chunks of 64,
// cp.async double buffer (2 x 64KB dynamic smem).
// MODE 0: A = x splits,  B = gwin_t,  epilogue scatters bf16 splits to q/k/v.
// MODE 1: A = ao splits, B = gwout_t, epilogue writes fp32 to Cout.
// ---------------------------------------------------------------------------
#define GEMM_SMEM_BYTES 131072

template<int NC, int MODE>
__global__ __launch_bounds__(256)
void mma_gemm_kernel(const float* __restrict__ bias, float* __restrict__ Cout) {
    extern __shared__ char smraw[];
    const uint32_t sb = smem_to_u32(smraw);
    const int tid = threadIdx.x, lane = tid & 31, wid = tid >> 5;
    const int wm = wid & 1, wn = wid >> 1;
    const int bm = blockIdx.y * 128, bn = blockIdx.x * 128;

    const __nv_bfloat16* A0 = MODE ? gao0 : gx0;
    const __nv_bfloat16* A1 = MODE ? gao1 : gx1;
    const __nv_bfloat16* B0 = MODE ? gwout_t0 : gwin_t0;
    const __nv_bfloat16* B1 = MODE ? gwout_t1 : gwin_t1;

    float acc[4][4][4];
#pragma unroll
    for (int mi = 0; mi < 4; mi++)
#pragma unroll
        for (int nj = 0; nj < 4; nj++)
#pragma unroll
            for (int u = 0; u < 4; u++) acc[mi][nj][u] = 0.f;

    gemm_load_stage(sb, tid, bm, bn, 0, A0, A1, B0, B1);
    CP_COMMIT();

    for (int i = 0; i < 16; i++) {
        if (i < 15) {
            gemm_load_stage(sb + (uint32_t)(((i + 1) & 1) * 65536), tid, bm, bn,
                            (i + 1) * 64, A0, A1, B0, B1);
            CP_COMMIT();
            CP_WAIT1();
        } else {
            CP_WAIT0();
        }
        __syncthreads();
        const uint32_t base = sb + (uint32_t)((i & 1) * 65536);
#pragma unroll
        for (int ks = 0; ks < 4; ks++) {
            uint32_t af0[4][4], af1[4][4], bf0[4][2], bf1[4][2];
#pragma unroll
            for (int mi = 0; mi < 4; mi++) {
                int row = wm * 64 + mi * 16 + (lane & 15);
                int ch = ks * 2 + (lane >> 4);
                uint32_t ad = base + row * 128 + ((ch ^ (row & 7)) << 4);
                ldmx4(af0[mi], ad);
                ldmx4(af1[mi], ad + 16384);
            }
#pragma unroll
            for (int nj = 0; nj < 4; nj++) {
                int rowb = wn * 32 + nj * 8 + (lane & 7);
                int chb = ks * 2 + ((lane >> 3) & 1);
                uint32_t bd = base + 32768 + rowb * 128 + ((chb ^ (rowb & 7)) << 4);
                ldmx2(bf0[nj], bd);
                ldmx2(bf1[nj], bd + 16384);
            }
#pragma unroll
            for (int mi = 0; mi < 4; mi++)
#pragma unroll
                for (int nj = 0; nj < 4; nj++) {
                    mma16816(acc[mi][nj], af0[mi], bf0[nj]);
                    mma16816(acc[mi][nj], af0[mi], bf1[nj]);
                    mma16816(acc[mi][nj], af1[mi], bf0[nj]);
                }
        }
        __syncthreads();
    }

    // ---- epilogue ----
    const int rl = lane >> 2, cl = (lane & 3) * 2;
#pragma unroll
    for (int mi = 0; mi < 4; mi++) {
#pragma unroll
        for (int nj = 0; nj < 4; nj++) {
            int c = bn + wn * 32 + nj * 8 + cl;
            float bv0 = bias[c], bv1 = bias[c + 1];
#pragma unroll
            for (int hf = 0; hf < 2; hf++) {
                int r = bm + wm * 64 + mi * 16 + rl + hf * 8;
                float v0 = acc[mi][nj][hf * 2 + 0] + bv0;
                float v1 = acc[mi][nj][hf * 2 + 1] + bv1;
                if (MODE == 0) {
                    int which = c >> 10;
                    int hh = (c >> 6) & 15;
                    int hd = c & 63;
                    int bb = r >> 11, n = r & 2047;
                    if (which == 2) { float g = g_gate[r]; v0 *= g; v1 *= g; }
                    size_t o = (((size_t)(bb * 16 + hh) * 2048 + n) << 6) + hd;
                    uint32_t hi, lo;
                    split2(v0, v1, hi, lo);
                    __nv_bfloat16 *p0, *p1;
                    if (which == 0)      { p0 = gq0; p1 = gq1; }
                    else if (which == 1) { p0 = gk0; p1 = gk1; }
                    else                 { p0 = gv0; p1 = gv1; }
                    *(uint32_t*)(p0 + o) = hi;
                    *(uint32_t*)(p1 + o) = lo;
                } else {
                    *(float2*)(Cout + (size_t)r * 1024 + c) = make_float2(v0, v1);
                }
            }
        }
    }
}

// ---------------------------------------------------------------------------
// Tensorized flash attention. Grid (16, H, B), 256 threads (8 warps).
// Q tile 128 (warp w: rows 16w..16w+15), key tiles of 64.
// S = QK^T via 3-chain bf16 mma (hi/lo splits); softmax on C-fragments;
// P fragments re-packed (split) directly as PV A-fragments; V via ldmatrix.trans.
// smem: Q0 @0, Q1 @16K, K0 @32K, K1 @40K, V0 @48K, V1 @56K, bias @64K.
// ---------------------------------------------------------------------------
#define ATTN_SMEM_BYTES 66048

__global__ __launch_bounds__(256)
void attn_mma_kernel() {
    extern __shared__ char smraw[];
    const uint32_t sb = smem_to_u32(smraw);
    float* biass = (float*)(smraw + 65536);
    const int b = blockIdx.z, h = blockIdx.y, q0 = blockIdx.x * 128;
    const int tid = threadIdx.x, lane = tid & 31, wid = tid >> 5;
    const size_t hb = ((size_t)(b * 16 + h)) << 17;   // *2048*64

    // ---- load Q tile (both splits), swizzled ----
#pragma unroll
    for (int p = 0; p < 4; p++) {
        int idx = tid + p * 256;
        int r = idx >> 3, c = idx & 7;
        uint32_t soff = (uint32_t)(r * 128 + ((c ^ (r & 7)) << 4));
        size_t go = hb + ((size_t)(q0 + r) << 6) + c * 8;
        CP_ASYNC16(sb + soff,         gq0 + go);
        CP_ASYNC16(sb + 16384 + soff, gq1 + go);
    }
    CP_COMMIT();
    CP_WAIT0();
    __syncthreads();

    // ---- preload Q fragments (persist across key tiles) ----
    uint32_t qf0[4][4], qf1[4][4];
#pragma unroll
    for (int ks = 0; ks < 4; ks++) {
        int row = wid * 16 + (lane & 15);
        int ch = ks * 2 + (lane >> 4);
        uint32_t ad = sb + row * 128 + ((ch ^ (row & 7)) << 4);
        ldmx4(qf0[ks], ad);
        ldmx4(qf1[ks], ad + 16384);
    }

    float ofr[8][4];
#pragma unroll
    for (int j = 0; j < 8; j++)
#pragma unroll
        for (int u = 0; u < 4; u++) ofr[j][u] = 0.f;
    float m0 = -1e30f, m1 = -1e30f, l0 = 0.f, l1 = 0.f;
    const float scale = 0.125f;   // 1/sqrt(64)

    for (int kt = 0; kt < NN; kt += 64) {
        __syncthreads();          // guard prior tile's K/V reads
#pragma unroll
        for (int p = 0; p < 2; p++) {
            int idx = tid + p * 256;
            int r = idx >> 3, c = idx & 7;
            uint32_t soff = (uint32_t)(r * 128 + ((c ^ (r & 7)) << 4));
            size_t go = hb + ((size_t)(kt + r) << 6) + c * 8;
            CP_ASYNC16(sb + 32768 + soff, gk0 + go);
            CP_ASYNC16(sb + 40960 + soff, gk1 + go);
            CP_ASYNC16(sb + 49152 + soff, gv0 + go);
            CP_ASYNC16(sb + 57344 + soff, gv1 + go);
        }
        if (tid < 16)
            CP_ASYNC16(sb + 65536 + tid * 16, g_bias + b * 2048 + kt + tid * 4);
        CP_COMMIT();
        CP_WAIT0();
        __syncthreads();

        // ---- S = Q K^T : 8 n-tiles x 4 k-steps x 3 split-chains ----
        float sfr[8][4];
#pragma unroll
        for (int j = 0; j < 8; j++) {
            sfr[j][0] = sfr[j][1] = sfr[j][2] = sfr[j][3] = 0.f;
#pragma unroll
            for (int ks = 0; ks < 4; ks++) {
                int rowb = j * 8 + (lane & 7);
                int chb = ks * 2 + ((lane >> 3) & 1);
                uint32_t bd = sb + 32768 + rowb * 128 + ((chb ^ (rowb & 7)) << 4);
                uint32_t k0f[2], k1f[2];
                ldmx2(k0f, bd);
                ldmx2(k1f, bd + 8192);
                mma16816(sfr[j], qf0[ks], k0f);
                mma16816(sfr[j], qf0[ks], k1f);
                mma16816(sfr[j], qf1[ks], k0f);
            }
        }

        // ---- online softmax on fragments (rows r=lane>>2 and r+8) ----
        float tm0 = -1e30f, tm1 = -1e30f;
#pragma unroll
        for (int j = 0; j < 8; j++) {
            int c = j * 8 + (lane & 3) * 2;
            float bv0 = biass[c], bv1 = biass[c + 1];
            sfr[j][0] = fmaf(sfr[j][0], scale, bv0);
            sfr[j][1] = fmaf(sfr[j][1], scale, bv1);
            sfr[j][2] = fmaf(sfr[j][2], scale, bv0);
            sfr[j][3] = fmaf(sfr[j][3], scale, bv1);
            tm0 = fmaxf(tm0, fmaxf(sfr[j][0], sfr[j][1]));
            tm1 = fmaxf(tm1, fmaxf(sfr[j][2], sfr[j][3]));
        }
        tm0 = fmaxf(tm0, __shfl_xor_sync(0xffffffffu, tm0, 1));
        tm0 = fmaxf(tm0, __shfl_xor_sync(0xffffffffu, tm0, 2));
        tm1 = fmaxf(tm1, __shfl_xor_sync(0xffffffffu, tm1, 1));
        tm1 = fmaxf(tm1, __shfl_xor_sync(0xffffffffu, tm1, 2));
        float mn0 = fmaxf(m0, tm0), mn1 = fmaxf(m1, tm1);
        float f0 = __expf(m0 - mn0), f1 = __expf(m1 - mn1);
        m0 = mn0; m1 = mn1;
        float ps0 = 0.f, ps1 = 0.f;
#pragma unroll
        for (int j = 0; j < 8; j++) {
            sfr[j][0] = __expf(sfr[j][0] - mn0);
            sfr[j][1] = __expf(sfr[j][1] - mn0);
            sfr[j][2] = __expf(sfr[j][2] - mn1);
            sfr[j][3] = __expf(sfr[j][3] - mn1);
            ps0 += sfr[j][0] + sfr[j][1];
            ps1 += sfr[j][2] + sfr[j][3];
        }
        ps0 += __shfl_xor_sync(0xffffffffu, ps0, 1);
        ps0 += __shfl_xor_sync(0xffffffffu, ps0, 2);
        ps1 += __shfl_xor_sync(0xffffffffu, ps1, 1);
        ps1 += __shfl_xor_sync(0xffffffffu, ps1, 2);
        l0 = l0 * f0 + ps0;
        l1 = l1 * f1 + ps1;
#pragma unroll
        for (int j = 0; j < 8; j++) {
            ofr[j][0] *= f0; ofr[j][1] *= f0;
            ofr[j][2] *= f1; ofr[j][3] *= f1;
        }

        // ---- O += P V : P from S fragments (hi/lo split), V via ldmatrix.trans
#pragma unroll
        for (int ks = 0; ks < 4; ks++) {
            uint32_t pa0[4], pa1[4];
            split2(sfr[2*ks][0],   sfr[2*ks][1],   pa0[0], pa1[0]);
            split2(sfr[2*ks][2],   sfr[2*ks][3],   pa0[1], pa1[1]);
            split2(sfr[2*ks+1][0], sfr[2*ks+1][1], pa0[2], pa1[2]);
            split2(sfr[2*ks+1][2], sfr[2*ks+1][3], pa0[3], pa1[3]);
            int rowv = ks * 16 + (lane & 15);
#pragma unroll
            for (int j2 = 0; j2 < 8; j2++) {
                uint32_t vd = sb + 49152 + rowv * 128 + ((j2 ^ (rowv & 7)) << 4);
                uint32_t v0f[2], v1f[2];
                ldmx2t(v0f, vd);
                ldmx2t(v1f, vd + 8192);
                mma16816(ofr[j2], pa0, v0f);
                mma16816(ofr[j2], pa0, v1f);
                mma16816(ofr[j2], pa1, v0f);
            }
        }
    }

    // ---- finalize: /l, split to bf16 hi/lo, write gao [B*N, D] ----
    float inv0 = 1.f / l0, inv1 = 1.f / l1;
    int r0 = q0 + wid * 16 + (lane >> 2);
    size_t t0 = ((size_t)(b * 2048 + r0)) << 10;
    size_t t1 = t0 + (8u << 10);
#pragma unroll
    for (int j2 = 0; j2 < 8; j2++) {
        int c = h * 64 + j2 * 8 + (lane & 3) * 2;
        uint32_t hi, lo;
        split2(ofr[j2][0] * inv0, ofr[j2][1] * inv0, hi, lo);
        *(uint32_t*)(gao0 + t0 + c) = hi;
        *(uint32_t*)(gao1 + t0 + c) = lo;
        split2(ofr[j2][2] * inv1, ofr[j2][3] * inv1, hi, lo);
        *(uint32_t*)(gao0 + t1 + c) = hi;
        *(uint32_t*)(gao1 + t1 + c) = lo;
    }
}

// ---------------------------------------------------------------------------
extern "C" void kernel_launch(void* const* d_in, const int* in_sizes, int n_in,
                              void* d_out, int out_size) {
    const float* x      = (const float*)d_in[0];
    const float* ppr    = (const float*)d_in[1];
    const float* trust  = (const float*)d_in[2];
    const float* W_in   = (const float*)d_in[3];
    const float* b_in   = (const float*)d_in[4];
    const float* W_out  = (const float*)d_in[5];
    const float* b_out  = (const float*)d_in[6];
    const float* alpha  = (const float*)d_in[7];
    const float* tsc    = (const float*)d_in[8];
    const int*   nctx_p = (n_in > 9) ? (const int*)d_in[9] : nullptr;
    float* out = (float*)d_out;

    cudaFuncSetAttribute(mma_gemm_kernel<3 * DD, 0>,
                         cudaFuncAttributeMaxDynamicSharedMemorySize, GEMM_SMEM_BYTES);
    cudaFuncSetAttribute(mma_gemm_kernel<DD, 1>,
                         cudaFuncAttributeMaxDynamicSharedMemorySize, GEMM_SMEM_BYTES);
    cudaFuncSetAttribute(attn_mma_kernel,
                         cudaFuncAttributeMaxDynamicSharedMemorySize, ATTN_SMEM_BYTES);

    gate_bias_kernel<<<(MTOT + 255) / 256, 256>>>(ppr, trust, alpha, tsc, nctx_p);
    split_x_kernel<<<((size_t)MTOT * DD / 4) / 256, 256>>>(x);
    tsplit_kernel<<<dim3(3 * DD / 32, DD / 32), dim3(32, 8)>>>(W_in, 3 * DD, 0);
    tsplit_kernel<<<dim3(DD / 32, DD / 32), dim3(32, 8)>>>(W_out, DD, 1);
    mma_gemm_kernel<3 * DD, 0><<<dim3(3 * DD / 128, MTOT / 128), 256, GEMM_SMEM_BYTES>>>(b_in, nullptr);
    attn_mma_kernel<<<dim3(NN / 128, HH, BB), 256, ATTN_SMEM_BYTES>>>();
    mma_gemm_kernel<DD, 1><<<dim3(DD / 128, MTOT / 128), 256, GEMM_SMEM_BYTES>>>(b_out, out);
}